// round 6
// baseline (speedup 1.0000x reference)
#include <cuda_runtime.h>

#define B_ 128
#define T_ 4096
#define I_ 64
#define H_ 128
#define G_ 384   /* 3*H */
#define C_ 2
#define ALPHA_ 0.3f
#define BETA_  0.5f

#define CH_   256   /* EMA chunk length  */
#define HALO_ 64    /* EMA warm-up halo: trunc err ~0.5^64 */

// Scratch (device globals: allocation-free per harness rules)
__device__ float g_x2[(long)B_ * T_ * I_];            // 134 MB
__device__ float g_xp[(long)B_ * T_ * G_ + 2 * G_];   // 805 MB (+2-row pad)
__device__ float g_st11[B_ * C_];
__device__ float g_st12[B_ * C_];

// ---------------- packed f32x2 helpers (sm_100+) ----------------
__device__ __forceinline__ unsigned long long pack2_(float lo, float hi) {
    unsigned long long r;
    asm("mov.b64 %0, {%1, %2};" : "=l"(r) : "f"(lo), "f"(hi));
    return r;
}
__device__ __forceinline__ float2 unpack2_(unsigned long long v) {
    float2 r;
    asm("mov.b64 {%0, %1}, %2;" : "=f"(r.x), "=f"(r.y) : "l"(v));
    return r;
}
__device__ __forceinline__ void fma2_(unsigned long long& d,
                                      unsigned long long a,
                                      unsigned long long b) {
    asm("fma.rn.f32x2 %0, %1, %2, %0;" : "+l"(d) : "l"(a), "l"(b));
}
// HW tanh (sm_75+): 1 MUFU, saturates to +-1, ~1e-4 rel err
__device__ __forceinline__ float tanh_hw_(float x) {
    float r;
    asm("tanh.approx.f32 %0, %1;" : "=f"(r) : "f"(x));
    return r;
}
__device__ __forceinline__ float sigm_hw_(float x) {
    return fmaf(tanh_hw_(0.5f * x), 0.5f, 0.5f);
}

// ---------------------------------------------------------------------------
// Kernel 1: chained EMAs, chunked-parallel with decay halo.
// ---------------------------------------------------------------------------
__global__ __launch_bounds__(64) void ema_kernel(const float* __restrict__ x) {
    int nchunk = T_ / CH_;
    int c = blockIdx.x % nchunk;
    int b = blockIdx.x / nchunk;
    int i = threadIdx.x;

    const float* xin = x + (long)b * T_ * I_ + i;
    float* o = g_x2 + (long)b * T_ * I_ + i;

    int t0 = c * CH_;
    int ts = (c == 0) ? 0 : (t0 - HALO_);

    float x1 = xin[(long)ts * I_];
    float x2 = x1;

#pragma unroll 4
    for (int t = ts + 1; t < t0; ++t) {
        float xt = xin[(long)t * I_];
        x1 = fmaf(ALPHA_, x1, (1.f - ALPHA_) * xt);
        x2 = fmaf(BETA_, x2, (1.f - BETA_) * x1);
    }

    if (c == 0) o[0] = x2;
    int tb = (c == 0) ? 1 : t0;
#pragma unroll 4
    for (int t = tb; t < t0 + CH_; ++t) {
        float xt = xin[(long)t * I_];
        x1 = fmaf(ALPHA_, x1, (1.f - ALPHA_) * xt);
        x2 = fmaf(BETA_, x2, (1.f - BETA_) * x1);
        o[(long)t * I_] = x2;
    }

    if (c == nchunk - 1 && (i == 1 || i == 2)) {
        g_st11[b * C_ + (i - 1)] = x1;
        g_st12[b * C_ + (i - 1)] = x2;
    }
}

// ---------------------------------------------------------------------------
// Kernel 2: xp[m, g] = b_ih[g] + sum_k x2[m, k] * W_ih[g, k]   (f32x2 packed)
// ---------------------------------------------------------------------------
__global__ __launch_bounds__(384) void xp_gemm_kernel(
    const float* __restrict__ W_ih, const float* __restrict__ b_ih) {
    __shared__ __align__(16) float xs[64 * I_];  // 16 KB
    int m0 = blockIdx.x * 64;
    int g = threadIdx.x;

    {
        const float4* src = (const float4*)(g_x2 + (long)m0 * I_);
        float4* dst = (float4*)xs;
        for (int idx = g; idx < (64 * I_) / 4; idx += 384) dst[idx] = src[idx];
    }

    unsigned long long w2[I_ / 2];
    {
        const unsigned long long* wrow =
            (const unsigned long long*)(W_ih + g * I_);
#pragma unroll
        for (int k = 0; k < I_ / 2; ++k) w2[k] = wrow[k];
    }
    float bias = b_ih[g];
    __syncthreads();

    for (int r = 0; r < 64; ++r) {
        unsigned long long acc0 = pack2_(bias, 0.f);
        unsigned long long acc1 = pack2_(0.f, 0.f);
        const ulonglong2* row8 = (const ulonglong2*)(xs + r * I_);
#pragma unroll
        for (int k = 0; k < I_ / 4; ++k) {
            ulonglong2 v = row8[k];
            fma2_(acc0, w2[2 * k + 0], v.x);
            fma2_(acc1, w2[2 * k + 1], v.y);
        }
        float2 a0 = unpack2_(acc0);
        float2 a1 = unpack2_(acc1);
        g_xp[(long)(m0 + r) * G_ + g] = (a0.x + a1.x) + (a0.y + a1.y);
    }
}

// ---------------------------------------------------------------------------
// Kernel 3: GRU scan. One CTA per batch, 384 threads (R2 shape).
// Thread g owns W_hh row g: 64 f32x2 regs. Partial unroll keeps live temps
// low (no spills). gi prefetch depth 2. HW tanh gates.
// ---------------------------------------------------------------------------
__global__ __launch_bounds__(384, 1) void gru_kernel(
    const float* __restrict__ W_hh, const float* __restrict__ b_hh,
    const float* __restrict__ W_fc, const float* __restrict__ b_fc,
    float* __restrict__ out) {
    __shared__ __align__(16) float sh[H_];   // hidden state
    __shared__ float sA[2 * H_];             // r,z pre-activations (gi+gh)
    __shared__ float sGn[H_];                // i_n
    __shared__ float sHn[H_];                // gh_n

    int b = blockIdx.x;
    int g = threadIdx.x;

    // full W_hh row in registers: 64 x f32x2 = 128 regs
    unsigned long long w2[H_ / 2];
    {
        const unsigned long long* wrow =
            (const unsigned long long*)(W_hh + g * H_);
#pragma unroll
        for (int k = 0; k < H_ / 2; ++k) w2[k] = wrow[k];
    }
    float bias = b_hh[g];

    if (g < H_) sh[g] = 0.f;

    // gi stream, prefetch depth 2
    const float* gp = g_xp + (long)b * T_ * G_ + g;
    float gi0 = gp[0];
    float gi1 = gp[G_];
    gp += 2 * G_;
    __syncthreads();

    const unsigned long long* h2 = (const unsigned long long*)sh;

    for (int t = 0; t < T_; ++t) {
        float gi2 = *gp;                      // prefetch t+2 (padded tail)
        gp += G_;

        unsigned long long acc0 = pack2_(bias, 0.f);
        unsigned long long acc1 = pack2_(0.f, 0.f);
        // partial unroll: limits live LDS temps -> no register spills
#pragma unroll 8
        for (int k = 0; k < H_ / 2; k += 2) {
            unsigned long long hva = h2[k];       // LDS.64, warp-broadcast
            unsigned long long hvb = h2[k + 1];
            fma2_(acc0, w2[k], hva);
            fma2_(acc1, w2[k + 1], hvb);
        }
        float2 a0 = unpack2_(acc0);
        float2 a1 = unpack2_(acc1);
        float acc = (a0.x + a1.x) + (a0.y + a1.y);

        if (g < 2 * H_) {
            sA[g] = gi0 + acc;                // r,z pre-activations
        } else {
            sGn[g - 2 * H_] = gi0;            // i_n (kept separate)
            sHn[g - 2 * H_] = acc;            // gh_n
        }
        __syncthreads();

        if (g < H_) {
            float r = sigm_hw_(sA[g]);
            float z = sigm_hw_(sA[H_ + g]);
            float n = tanh_hw_(fmaf(r, sHn[g], sGn[g]));
            sh[g] = fmaf(z, sh[g] - n, n);    // (1-z)n + z h
        }
        __syncthreads();
        gi0 = gi1;
        gi1 = gi2;
    }

    if (g < C_) {
        float o = b_fc[g];
        const float* wf = W_fc + g * H_;
#pragma unroll 8
        for (int j = 0; j < H_; ++j) o = fmaf(sh[j], wf[j], o);
        o = (o - BETA_ * g_st12[b * C_ + g]) / (1.f - BETA_);
        o = (o - ALPHA_ * g_st11[b * C_ + g]) / (1.f - ALPHA_);
        out[b * C_ + g] = o;
    }
}

// ---------------------------------------------------------------------------
extern "C" void kernel_launch(void* const* d_in, const int* in_sizes, int n_in,
                              void* d_out, int out_size) {
    const float* x    = (const float*)d_in[0];
    const float* W_ih = (const float*)d_in[1];
    const float* W_hh = (const float*)d_in[2];
    const float* b_ih = (const float*)d_in[3];
    const float* b_hh = (const float*)d_in[4];
    const float* W_fc = (const float*)d_in[5];
    const float* b_fc = (const float*)d_in[6];
    float* out = (float*)d_out;

    ema_kernel<<<B_ * (T_ / CH_), 64>>>(x);
    xp_gemm_kernel<<<(B_ * T_) / 64, 384>>>(W_ih, b_ih);
    gru_kernel<<<B_, 384>>>(W_hh, b_hh, W_fc, b_fc, out);
}

// round 7
// speedup vs baseline: 2.2979x; 2.2979x over previous
#include <cuda_runtime.h>

#define B_ 128
#define T_ 4096
#define I_ 64
#define H_ 128
#define G_ 384   /* 3*H */
#define C_ 2
#define ALPHA_ 0.3f
#define BETA_  0.5f

#define CH_   256   /* EMA chunk length  */
#define HALO_ 64    /* EMA warm-up halo: trunc err ~0.5^64 */

// Scratch (device globals: allocation-free per harness rules)
__device__ float g_x2[(long)B_ * T_ * I_];            // 134 MB
__device__ float g_xp[(long)B_ * T_ * G_ + 3 * G_];   // 805 MB (+3-row pad)
__device__ float g_st11[B_ * C_];
__device__ float g_st12[B_ * C_];

// ---------------- packed f32x2 helpers (sm_100+) ----------------
__device__ __forceinline__ unsigned long long pack2_(float lo, float hi) {
    unsigned long long r;
    asm("mov.b64 %0, {%1, %2};" : "=l"(r) : "f"(lo), "f"(hi));
    return r;
}
__device__ __forceinline__ float2 unpack2_(unsigned long long v) {
    float2 r;
    asm("mov.b64 {%0, %1}, %2;" : "=f"(r.x), "=f"(r.y) : "l"(v));
    return r;
}
__device__ __forceinline__ void fma2_(unsigned long long& d,
                                      unsigned long long a,
                                      unsigned long long b) {
    asm("fma.rn.f32x2 %0, %1, %2, %0;" : "+l"(d) : "l"(a), "l"(b));
}
// HW tanh (sm_75+): single MUFU op, saturates naturally, ~1e-5 rel err
__device__ __forceinline__ float tanh_hw_(float x) {
    float r;
    asm("tanh.approx.f32 %0, %1;" : "=f"(r) : "f"(x));
    return r;
}
__device__ __forceinline__ float sigm_hw_(float x) {
    return fmaf(tanh_hw_(0.5f * x), 0.5f, 0.5f);
}

// ---------------------------------------------------------------------------
// Kernel 1: chained EMAs, chunked-parallel with decay halo.  (R2, unchanged)
// ---------------------------------------------------------------------------
__global__ __launch_bounds__(64) void ema_kernel(const float* __restrict__ x) {
    int nchunk = T_ / CH_;
    int c = blockIdx.x % nchunk;
    int b = blockIdx.x / nchunk;
    int i = threadIdx.x;

    const float* xin = x + (long)b * T_ * I_ + i;
    float* o = g_x2 + (long)b * T_ * I_ + i;

    int t0 = c * CH_;
    int ts = (c == 0) ? 0 : (t0 - HALO_);

    float x1 = xin[(long)ts * I_];
    float x2 = x1;

#pragma unroll 4
    for (int t = ts + 1; t < t0; ++t) {
        float xt = xin[(long)t * I_];
        x1 = fmaf(ALPHA_, x1, (1.f - ALPHA_) * xt);
        x2 = fmaf(BETA_, x2, (1.f - BETA_) * x1);
    }

    if (c == 0) o[0] = x2;
    int tb = (c == 0) ? 1 : t0;
#pragma unroll 4
    for (int t = tb; t < t0 + CH_; ++t) {
        float xt = xin[(long)t * I_];
        x1 = fmaf(ALPHA_, x1, (1.f - ALPHA_) * xt);
        x2 = fmaf(BETA_, x2, (1.f - BETA_) * x1);
        o[(long)t * I_] = x2;
    }

    if (c == nchunk - 1 && (i == 1 || i == 2)) {
        g_st11[b * C_ + (i - 1)] = x1;
        g_st12[b * C_ + (i - 1)] = x2;
    }
}

// ---------------------------------------------------------------------------
// Kernel 2: xp = x2 @ W_ih^T + b_ih  (f32x2 packed; R2, unchanged)
// ---------------------------------------------------------------------------
__global__ __launch_bounds__(384) void xp_gemm_kernel(
    const float* __restrict__ W_ih, const float* __restrict__ b_ih) {
    __shared__ __align__(16) float xs[64 * I_];  // 16 KB
    int m0 = blockIdx.x * 64;
    int g = threadIdx.x;

    {
        const float4* src = (const float4*)(g_x2 + (long)m0 * I_);
        float4* dst = (float4*)xs;
        for (int idx = g; idx < (64 * I_) / 4; idx += 384) dst[idx] = src[idx];
    }

    unsigned long long w2[I_ / 2];
    {
        const unsigned long long* wrow =
            (const unsigned long long*)(W_ih + g * I_);
#pragma unroll
        for (int k = 0; k < I_ / 2; ++k) w2[k] = wrow[k];
    }
    float bias = b_ih[g];
    __syncthreads();

    for (int r = 0; r < 64; ++r) {
        unsigned long long acc0 = pack2_(bias, 0.f);
        unsigned long long acc1 = pack2_(0.f, 0.f);
        const ulonglong2* row8 = (const ulonglong2*)(xs + r * I_);
#pragma unroll
        for (int k = 0; k < I_ / 4; ++k) {
            ulonglong2 v = row8[k];
            fma2_(acc0, w2[2 * k + 0], v.x);
            fma2_(acc1, w2[2 * k + 1], v.y);
        }
        float2 a0 = unpack2_(acc0);
        float2 a1 = unpack2_(acc1);
        g_xp[(long)(m0 + r) * G_ + g] = (a0.x + a1.x) + (a0.y + a1.y);
    }
}

// ---------------------------------------------------------------------------
// Kernel 3: GRU scan — R2 structure (384 thr, full row, FULL unroll,
// LDS.128) with hw-tanh gates and prefetch depth 3.
// ---------------------------------------------------------------------------
__global__ __launch_bounds__(384, 1) void gru_kernel(
    const float* __restrict__ W_hh, const float* __restrict__ b_hh,
    const float* __restrict__ W_fc, const float* __restrict__ b_fc,
    float* __restrict__ out) {
    __shared__ __align__(16) float sh[H_];   // hidden state
    __shared__ float sA[2 * H_];             // r,z pre-activations (gi+gh)
    __shared__ float sGn[H_];                // i_n
    __shared__ float sHn[H_];                // gh_n

    int b = blockIdx.x;
    int g = threadIdx.x;

    // full W_hh row in registers: 64 x f32x2 = 128 regs (STATIC indexing only)
    unsigned long long w2[H_ / 2];
    {
        const unsigned long long* wrow =
            (const unsigned long long*)(W_hh + g * H_);
#pragma unroll
        for (int k = 0; k < H_ / 2; ++k) w2[k] = wrow[k];
    }
    float bias = b_hh[g];

    if (g < H_) sh[g] = 0.f;

    // gi stream, prefetch depth 3
    const float* gp = g_xp + (long)b * T_ * G_ + g;
    float gi0 = gp[0];
    float gi1 = gp[G_];
    float gi2 = gp[2 * G_];
    gp += 3 * G_;
    __syncthreads();

    const ulonglong2* h8 = (const ulonglong2*)sh;

    for (int t = 0; t < T_; ++t) {
        float gi3 = *gp;                      // prefetch t+3 (padded tail)
        gp += G_;

        unsigned long long acc0 = pack2_(bias, 0.f);
        unsigned long long acc1 = pack2_(0.f, 0.f);
#pragma unroll
        for (int k = 0; k < H_ / 4; ++k) {    // FULL unroll: static w2 idx
            ulonglong2 hv = h8[k];            // LDS.128, warp-broadcast
            fma2_(acc0, w2[2 * k + 0], hv.x);
            fma2_(acc1, w2[2 * k + 1], hv.y);
        }
        float2 a0 = unpack2_(acc0);
        float2 a1 = unpack2_(acc1);
        float acc = (a0.x + a1.x) + (a0.y + a1.y);

        if (g < 2 * H_) {
            sA[g] = gi0 + acc;                // r,z pre-activations
        } else {
            sGn[g - 2 * H_] = gi0;            // i_n (kept separate)
            sHn[g - 2 * H_] = acc;            // gh_n
        }
        __syncthreads();

        if (g < H_) {
            float r = sigm_hw_(sA[g]);
            float z = sigm_hw_(sA[H_ + g]);
            float n = tanh_hw_(fmaf(r, sHn[g], sGn[g]));
            sh[g] = fmaf(z, sh[g] - n, n);    // (1-z)n + z h
        }
        __syncthreads();
        gi0 = gi1;
        gi1 = gi2;
        gi2 = gi3;
    }

    if (g < C_) {
        float o = b_fc[g];
        const float* wf = W_fc + g * H_;
#pragma unroll 8
        for (int j = 0; j < H_; ++j) o = fmaf(sh[j], wf[j], o);
        o = (o - BETA_ * g_st12[b * C_ + g]) / (1.f - BETA_);
        o = (o - ALPHA_ * g_st11[b * C_ + g]) / (1.f - ALPHA_);
        out[b * C_ + g] = o;
    }
}

// ---------------------------------------------------------------------------
extern "C" void kernel_launch(void* const* d_in, const int* in_sizes, int n_in,
                              void* d_out, int out_size) {
    const float* x    = (const float*)d_in[0];
    const float* W_ih = (const float*)d_in[1];
    const float* W_hh = (const float*)d_in[2];
    const float* b_ih = (const float*)d_in[3];
    const float* b_hh = (const float*)d_in[4];
    const float* W_fc = (const float*)d_in[5];
    const float* b_fc = (const float*)d_in[6];
    float* out = (float*)d_out;

    ema_kernel<<<B_ * (T_ / CH_), 64>>>(x);
    xp_gemm_kernel<<<(B_ * T_) / 64, 384>>>(W_ih, b_ih);
    gru_kernel<<<B_, 384>>>(W_hh, b_hh, W_fc, b_fc, out);
}

// round 8
// speedup vs baseline: 2.8583x; 1.2439x over previous
#include <cuda_runtime.h>

#define B_ 128
#define T_ 4096
#define I_ 64
#define H_ 128
#define G_ 384   /* 3*H */
#define C_ 2
#define ALPHA_ 0.3f
#define BETA_  0.5f

#define CH_   256   /* EMA chunk length  */
#define HALO_ 64    /* EMA warm-up halo: trunc err ~0.5^64 */

// Scratch (device globals: allocation-free per harness rules)
__device__ float g_x2[(long)B_ * T_ * I_];            // 134 MB
__device__ float g_xp[(long)B_ * T_ * G_ + 3 * G_];   // 805 MB (+3-row pad)
__device__ float g_st11[B_ * C_];
__device__ float g_st12[B_ * C_];

// ---------------- packed f32x2 helpers (sm_100+) ----------------
__device__ __forceinline__ unsigned long long pack2_(float lo, float hi) {
    unsigned long long r;
    asm("mov.b64 %0, {%1, %2};" : "=l"(r) : "f"(lo), "f"(hi));
    return r;
}
__device__ __forceinline__ float2 unpack2_(unsigned long long v) {
    float2 r;
    asm("mov.b64 {%0, %1}, %2;" : "=f"(r.x), "=f"(r.y) : "l"(v));
    return r;
}
__device__ __forceinline__ void fma2_(unsigned long long& d,
                                      unsigned long long a,
                                      unsigned long long b) {
    asm("fma.rn.f32x2 %0, %1, %2, %0;" : "+l"(d) : "l"(a), "l"(b));
}
__device__ __forceinline__ float tanh_hw_(float x) {
    float r;
    asm("tanh.approx.f32 %0, %1;" : "=f"(r) : "f"(x));
    return r;
}
__device__ __forceinline__ float sigm_hw_(float x) {
    return fmaf(tanh_hw_(0.5f * x), 0.5f, 0.5f);
}

// h swizzle: 16B chunk c = 4*s + q holds h[32q + 4s .. +4)  (s=0..7, q=0..3)
// -> word offset of h[j]: j=(q,s,e): 16s + 4q + e
__device__ __forceinline__ int hsw_word_(int j) {
    int q = j >> 5, s = (j >> 2) & 7, e = j & 3;
    return 16 * s + 4 * q + e;
}

// ---------------------------------------------------------------------------
// Kernel 1: chained EMAs, chunked-parallel with decay halo.  (unchanged)
// ---------------------------------------------------------------------------
__global__ __launch_bounds__(64) void ema_kernel(const float* __restrict__ x) {
    int nchunk = T_ / CH_;
    int c = blockIdx.x % nchunk;
    int b = blockIdx.x / nchunk;
    int i = threadIdx.x;

    const float* xin = x + (long)b * T_ * I_ + i;
    float* o = g_x2 + (long)b * T_ * I_ + i;

    int t0 = c * CH_;
    int ts = (c == 0) ? 0 : (t0 - HALO_);

    float x1 = xin[(long)ts * I_];
    float x2 = x1;

#pragma unroll 4
    for (int t = ts + 1; t < t0; ++t) {
        float xt = xin[(long)t * I_];
        x1 = fmaf(ALPHA_, x1, (1.f - ALPHA_) * xt);
        x2 = fmaf(BETA_, x2, (1.f - BETA_) * x1);
    }

    if (c == 0) o[0] = x2;
    int tb = (c == 0) ? 1 : t0;
#pragma unroll 4
    for (int t = tb; t < t0 + CH_; ++t) {
        float xt = xin[(long)t * I_];
        x1 = fmaf(ALPHA_, x1, (1.f - ALPHA_) * xt);
        x2 = fmaf(BETA_, x2, (1.f - BETA_) * x1);
        o[(long)t * I_] = x2;
    }

    if (c == nchunk - 1 && (i == 1 || i == 2)) {
        g_st11[b * C_ + (i - 1)] = x1;
        g_st12[b * C_ + (i - 1)] = x2;
    }
}

// ---------------------------------------------------------------------------
// Kernel 2: xp = x2 @ W_ih^T + b_ih  (f32x2 packed; unchanged)
// ---------------------------------------------------------------------------
__global__ __launch_bounds__(384) void xp_gemm_kernel(
    const float* __restrict__ W_ih, const float* __restrict__ b_ih) {
    __shared__ __align__(16) float xs[64 * I_];  // 16 KB
    int m0 = blockIdx.x * 64;
    int g = threadIdx.x;

    {
        const float4* src = (const float4*)(g_x2 + (long)m0 * I_);
        float4* dst = (float4*)xs;
        for (int idx = g; idx < (64 * I_) / 4; idx += 384) dst[idx] = src[idx];
    }

    unsigned long long w2[I_ / 2];
    {
        const unsigned long long* wrow =
            (const unsigned long long*)(W_ih + g * I_);
#pragma unroll
        for (int k = 0; k < I_ / 2; ++k) w2[k] = wrow[k];
    }
    float bias = b_ih[g];
    __syncthreads();

    for (int r = 0; r < 64; ++r) {
        unsigned long long acc0 = pack2_(bias, 0.f);
        unsigned long long acc1 = pack2_(0.f, 0.f);
        const ulonglong2* row8 = (const ulonglong2*)(xs + r * I_);
#pragma unroll
        for (int k = 0; k < I_ / 4; ++k) {
            ulonglong2 v = row8[k];
            fma2_(acc0, w2[2 * k + 0], v.x);
            fma2_(acc1, w2[2 * k + 1], v.y);
        }
        float2 a0 = unpack2_(acc0);
        float2 a1 = unpack2_(acc1);
        g_xp[(long)(m0 + r) * G_ + g] = (a0.x + a1.x) + (a0.y + a1.y);
    }
}

// ---------------------------------------------------------------------------
// Kernel 3: GRU scan — ONE barrier per step.
// 512 threads: thread (j = tid/4, p = tid%4). Each thread holds the p-th
// 32-wide K-quarter of W_hh rows {j, 128+j, 256+j} (48 f32x2 regs).
// One LDS.128 of swizzled h feeds all 3 accumulators. K-reduction via
// shfl.bfly within the 4-lane group; gates computed in-warp on all lanes;
// h_old kept in a register; only p==0 stores h[j]; single __syncthreads.
// ---------------------------------------------------------------------------
__global__ __launch_bounds__(512, 1) void gru_kernel(
    const float* __restrict__ W_hh, const float* __restrict__ b_hh,
    const float* __restrict__ W_fc, const float* __restrict__ b_fc,
    float* __restrict__ out) {
    __shared__ __align__(16) float shw[H_];  // swizzled hidden state

    int tid = threadIdx.x;
    int j = tid >> 2;
    int p = tid & 3;
    int lane = tid & 31;
    int b = blockIdx.x;

    // weight quarters: rows j (r), 128+j (z), 256+j (n), cols [32p, 32p+32)
    unsigned long long wr[16], wz[16], wn[16];
    {
        const unsigned long long* rr =
            (const unsigned long long*)(W_hh + (j)*H_ + 32 * p);
        const unsigned long long* rz =
            (const unsigned long long*)(W_hh + (H_ + j) * H_ + 32 * p);
        const unsigned long long* rn =
            (const unsigned long long*)(W_hh + (2 * H_ + j) * H_ + 32 * p);
#pragma unroll
        for (int k = 0; k < 16; ++k) { wr[k] = rr[k]; wz[k] = rz[k]; wn[k] = rn[k]; }
    }

    // per-lane bias constants (folded into pre-reduction accumulators)
    float b_r = (p == 0) ? b_hh[j] : 0.f;          // on p0
    float b_z = (p == 1) ? b_hh[H_ + j] : 0.f;     // on p1
    float b_n = (p == 1) ? b_hh[2 * H_ + j] : 0.f; // on p1

    // gi stream: p0 -> i_r, p1 -> i_z, p2 -> i_n, p3 -> dummy (i_n copy)
    int gcol = (p < 2) ? p * H_ + j : 2 * H_ + j;
    const float* gp = g_xp + (long)b * T_ * G_ + gcol;
    float gi0 = gp[0];
    float gi1 = gp[G_];
    gp += 2 * G_;

    if (tid < H_) shw[hsw_word_(tid)] = 0.f;
    float hprev = 0.f;

    // p==0 store pointer for h[j]
    float* hst = &shw[hsw_word_(j)];
    int src_in = (lane & ~3) | 2;   // lane holding i_n in this 4-group
    __syncthreads();

    const ulonglong2* hsw = (const ulonglong2*)shw;

    for (int t = 0; t < T_; ++t) {
        float gi2 = *gp;                      // prefetch t+2 (padded tail)
        gp += G_;

        unsigned long long ar = pack2_((p == 0) ? b_r + gi0 : 0.f, 0.f);
        unsigned long long az = pack2_((p == 1) ? b_z + gi0 : 0.f, 0.f);
        unsigned long long an = pack2_(b_n, 0.f);   // i_n NOT folded
#pragma unroll
        for (int s = 0; s < 8; ++s) {
            ulonglong2 hv = hsw[4 * s + p];   // 16B apart per lane: no conflict
            fma2_(ar, wr[2 * s + 0], hv.x);
            fma2_(ar, wr[2 * s + 1], hv.y);
            fma2_(az, wz[2 * s + 0], hv.x);
            fma2_(az, wz[2 * s + 1], hv.y);
            fma2_(an, wn[2 * s + 0], hv.x);
            fma2_(an, wn[2 * s + 1], hv.y);
        }
        float2 fr = unpack2_(ar);
        float2 fz = unpack2_(az);
        float2 fn = unpack2_(an);
        float Ar = fr.x + fr.y;
        float Az = fz.x + fz.y;
        float Gn = fn.x + fn.y;
        // reduce over the 4 K-quarters (lanes 4k..4k+3)
        Ar += __shfl_xor_sync(0xffffffffu, Ar, 1);
        Az += __shfl_xor_sync(0xffffffffu, Az, 1);
        Gn += __shfl_xor_sync(0xffffffffu, Gn, 1);
        Ar += __shfl_xor_sync(0xffffffffu, Ar, 2);
        Az += __shfl_xor_sync(0xffffffffu, Az, 2);
        Gn += __shfl_xor_sync(0xffffffffu, Gn, 2);
        float i_n = __shfl_sync(0xffffffffu, gi0, src_in);

        float r = sigm_hw_(Ar);
        float z = sigm_hw_(Az);
        float n = tanh_hw_(fmaf(r, Gn, i_n));
        hprev = fmaf(z, hprev - n, n);

        if (p == 0) *hst = hprev;
        __syncthreads();                      // ONE barrier per step

        gi0 = gi1;
        gi1 = gi2;
    }

    if (tid < C_) {
        float o = b_fc[tid];
        const float* wf = W_fc + tid * H_;
#pragma unroll 8
        for (int jj = 0; jj < H_; ++jj)
            o = fmaf(shw[hsw_word_(jj)], wf[jj], o);
        o = (o - BETA_ * g_st12[b * C_ + tid]) / (1.f - BETA_);
        o = (o - ALPHA_ * g_st11[b * C_ + tid]) / (1.f - ALPHA_);
        out[b * C_ + tid] = o;
    }
}

// ---------------------------------------------------------------------------
extern "C" void kernel_launch(void* const* d_in, const int* in_sizes, int n_in,
                              void* d_out, int out_size) {
    const float* x    = (const float*)d_in[0];
    const float* W_ih = (const float*)d_in[1];
    const float* W_hh = (const float*)d_in[2];
    const float* b_ih = (const float*)d_in[3];
    const float* b_hh = (const float*)d_in[4];
    const float* W_fc = (const float*)d_in[5];
    const float* b_fc = (const float*)d_in[6];
    float* out = (float*)d_out;

    ema_kernel<<<B_ * (T_ / CH_), 64>>>(x);
    xp_gemm_kernel<<<(B_ * T_) / 64, 384>>>(W_ih, b_ih);
    gru_kernel<<<B_, 512>>>(W_hh, b_hh, W_fc, b_fc, out);
}

// round 9
// speedup vs baseline: 3.0293x; 1.0599x over previous
#include <cuda_runtime.h>

#define B_ 128
#define T_ 4096
#define I_ 64
#define H_ 128
#define G_ 384   /* 3*H */
#define C_ 2
#define ALPHA_ 0.3f
#define BETA_  0.5f

#define CH_   256   /* EMA chunk length  */
#define HALO_ 64    /* EMA warm-up halo: trunc err ~0.5^64 */

// Scratch (device globals: allocation-free per harness rules)
__device__ float g_x2[(long)B_ * T_ * I_];            // 134 MB
__device__ float g_xp[(long)B_ * T_ * G_ + 3 * G_];   // 805 MB (+3-row pad)
__device__ float g_st11[B_ * C_];
__device__ float g_st12[B_ * C_];

// ---------------- packed f32x2 helpers (sm_100+) ----------------
__device__ __forceinline__ unsigned long long pack2_(float lo, float hi) {
    unsigned long long r;
    asm("mov.b64 %0, {%1, %2};" : "=l"(r) : "f"(lo), "f"(hi));
    return r;
}
__device__ __forceinline__ float2 unpack2_(unsigned long long v) {
    float2 r;
    asm("mov.b64 {%0, %1}, %2;" : "=f"(r.x), "=f"(r.y) : "l"(v));
    return r;
}
__device__ __forceinline__ void fma2_(unsigned long long& d,
                                      unsigned long long a,
                                      unsigned long long b) {
    asm("fma.rn.f32x2 %0, %1, %2, %0;" : "+l"(d) : "l"(a), "l"(b));
}
__device__ __forceinline__ float tanh_hw_(float x) {
    float r;
    asm("tanh.approx.f32 %0, %1;" : "=f"(r) : "f"(x));
    return r;
}
__device__ __forceinline__ float sigm_hw_(float x) {
    return fmaf(tanh_hw_(0.5f * x), 0.5f, 0.5f);
}

// 2-way h swizzle: 16B chunk (2k+p) holds half-p chunk k  (k=0..15)
// h[j]: p=j>>6, k=(j>>2)&15, e=j&3 -> word 8k + 4p + e
__device__ __forceinline__ int hsw2_word_(int j) {
    int p = j >> 6, k = (j >> 2) & 15, e = j & 3;
    return 8 * k + 4 * p + e;
}

// ---------------------------------------------------------------------------
// Kernel 1: chained EMAs, chunked-parallel with decay halo.  (unchanged)
// ---------------------------------------------------------------------------
__global__ __launch_bounds__(64) void ema_kernel(const float* __restrict__ x) {
    int nchunk = T_ / CH_;
    int c = blockIdx.x % nchunk;
    int b = blockIdx.x / nchunk;
    int i = threadIdx.x;

    const float* xin = x + (long)b * T_ * I_ + i;
    float* o = g_x2 + (long)b * T_ * I_ + i;

    int t0 = c * CH_;
    int ts = (c == 0) ? 0 : (t0 - HALO_);

    float x1 = xin[(long)ts * I_];
    float x2 = x1;

#pragma unroll 4
    for (int t = ts + 1; t < t0; ++t) {
        float xt = xin[(long)t * I_];
        x1 = fmaf(ALPHA_, x1, (1.f - ALPHA_) * xt);
        x2 = fmaf(BETA_, x2, (1.f - BETA_) * x1);
    }

    if (c == 0) o[0] = x2;
    int tb = (c == 0) ? 1 : t0;
#pragma unroll 4
    for (int t = tb; t < t0 + CH_; ++t) {
        float xt = xin[(long)t * I_];
        x1 = fmaf(ALPHA_, x1, (1.f - ALPHA_) * xt);
        x2 = fmaf(BETA_, x2, (1.f - BETA_) * x1);
        o[(long)t * I_] = x2;
    }

    if (c == nchunk - 1 && (i == 1 || i == 2)) {
        g_st11[b * C_ + (i - 1)] = x1;
        g_st12[b * C_ + (i - 1)] = x2;
    }
}

// ---------------------------------------------------------------------------
// Kernel 2: xp = x2 @ W_ih^T + b_ih  (f32x2 packed; unchanged)
// ---------------------------------------------------------------------------
__global__ __launch_bounds__(384) void xp_gemm_kernel(
    const float* __restrict__ W_ih, const float* __restrict__ b_ih) {
    __shared__ __align__(16) float xs[64 * I_];  // 16 KB
    int m0 = blockIdx.x * 64;
    int g = threadIdx.x;

    {
        const float4* src = (const float4*)(g_x2 + (long)m0 * I_);
        float4* dst = (float4*)xs;
        for (int idx = g; idx < (64 * I_) / 4; idx += 384) dst[idx] = src[idx];
    }

    unsigned long long w2[I_ / 2];
    {
        const unsigned long long* wrow =
            (const unsigned long long*)(W_ih + g * I_);
#pragma unroll
        for (int k = 0; k < I_ / 2; ++k) w2[k] = wrow[k];
    }
    float bias = b_ih[g];
    __syncthreads();

    for (int r = 0; r < 64; ++r) {
        unsigned long long acc0 = pack2_(bias, 0.f);
        unsigned long long acc1 = pack2_(0.f, 0.f);
        const ulonglong2* row8 = (const ulonglong2*)(xs + r * I_);
#pragma unroll
        for (int k = 0; k < I_ / 4; ++k) {
            ulonglong2 v = row8[k];
            fma2_(acc0, w2[2 * k + 0], v.x);
            fma2_(acc1, w2[2 * k + 1], v.y);
        }
        float2 a0 = unpack2_(acc0);
        float2 a1 = unpack2_(acc1);
        g_xp[(long)(m0 + r) * G_ + g] = (a0.x + a1.x) + (a0.y + a1.y);
    }
}

// ---------------------------------------------------------------------------
// Kernel 3: GRU scan — 2-way K-split, 256 threads, 3 shfls + 1 barrier/step.
// Thread (j = tid/2, p = tid&1): p-th 64-wide K-half of W_hh rows
// {j, 128+j, 256+j} -> 96 f32x2 regs (192 regs, full unroll, static idx).
// One xor-1 bfly stage reduces; gates on p0 only; p0 stores h[j].
// ---------------------------------------------------------------------------
__global__ __launch_bounds__(256, 1) void gru_kernel(
    const float* __restrict__ W_hh, const float* __restrict__ b_hh,
    const float* __restrict__ W_fc, const float* __restrict__ b_fc,
    float* __restrict__ out) {
    __shared__ __align__(16) float shw[H_];  // swizzled hidden state

    int tid = threadIdx.x;
    int j = tid >> 1;
    int p = tid & 1;
    int b = blockIdx.x;

    // weight halves: rows j (r), 128+j (z), 256+j (n), cols [64p, 64p+64)
    unsigned long long wr[32], wz[32], wn[32];
    {
        const unsigned long long* rr =
            (const unsigned long long*)(W_hh + (j)*H_ + 64 * p);
        const unsigned long long* rz =
            (const unsigned long long*)(W_hh + (H_ + j) * H_ + 64 * p);
        const unsigned long long* rn =
            (const unsigned long long*)(W_hh + (2 * H_ + j) * H_ + 64 * p);
#pragma unroll
        for (int k = 0; k < 32; ++k) { wr[k] = rr[k]; wz[k] = rz[k]; wn[k] = rn[k]; }
    }

    float b_r = b_hh[j];            // folded on p0
    float b_z = b_hh[H_ + j];       // folded on p1
    float b_n = b_hh[2 * H_ + j];   // folded on p1

    // gi streams (prefetch depth 2):
    //   stream A: p0 -> i_r (col j),      p1 -> i_z (col H+j)
    //   stream B: p0 -> i_n (col 2H+j),   p1 -> duplicate i_z (unused)
    const float* base = g_xp + (long)b * T_ * G_;
    const float* gpA = base + (p ? H_ + j : j);
    const float* gpB = base + (p ? H_ + j : 2 * H_ + j);
    float giA0 = gpA[0], giA1 = gpA[G_];
    float giB0 = gpB[0], giB1 = gpB[G_];
    gpA += 2 * G_;
    gpB += 2 * G_;

    if (tid < H_) shw[tid] = 0.f;
    float hprev = 0.f;
    float* hst = &shw[hsw2_word_(j)];
    __syncthreads();

    const ulonglong2* hsw = (const ulonglong2*)shw;

    for (int t = 0; t < T_; ++t) {
        float giA2 = *gpA; gpA += G_;         // prefetch t+2 (padded tail)
        float giB2 = *gpB; gpB += G_;

        unsigned long long ar = pack2_(p ? 0.f : b_r + giA0, 0.f);
        unsigned long long az = pack2_(p ? b_z + giA0 : 0.f, 0.f);
        unsigned long long an = pack2_(p ? b_n : 0.f, 0.f);
#pragma unroll
        for (int k = 0; k < 16; ++k) {        // FULL unroll: static idx
            ulonglong2 hv = hsw[2 * k + p];   // 16B apart per p: no conflict
            fma2_(ar, wr[2 * k + 0], hv.x);
            fma2_(ar, wr[2 * k + 1], hv.y);
            fma2_(az, wz[2 * k + 0], hv.x);
            fma2_(az, wz[2 * k + 1], hv.y);
            fma2_(an, wn[2 * k + 0], hv.x);
            fma2_(an, wn[2 * k + 1], hv.y);
        }
        float2 fr = unpack2_(ar);
        float2 fz = unpack2_(az);
        float2 fn = unpack2_(an);
        float Ar = fr.x + fr.y;
        float Az = fz.x + fz.y;
        float Gn = fn.x + fn.y;
        // single xor-1 reduction stage (partner lane)
        Ar += __shfl_xor_sync(0xffffffffu, Ar, 1);
        Az += __shfl_xor_sync(0xffffffffu, Az, 1);
        Gn += __shfl_xor_sync(0xffffffffu, Gn, 1);

        if (p == 0) {                         // gates + state on p0 only
            float r = sigm_hw_(Ar);
            float z = sigm_hw_(Az);
            float n = tanh_hw_(fmaf(r, Gn, giB0));  // giB0 = i_n
            hprev = fmaf(z, hprev - n, n);
            *hst = hprev;
        }
        __syncthreads();                      // ONE barrier per step

        giA0 = giA1; giA1 = giA2;
        giB0 = giB1; giB1 = giB2;
    }

    if (tid < C_) {
        float o = b_fc[tid];
        const float* wf = W_fc + tid * H_;
#pragma unroll 8
        for (int jj = 0; jj < H_; ++jj)
            o = fmaf(shw[hsw2_word_(jj)], wf[jj], o);
        o = (o - BETA_ * g_st12[b * C_ + tid]) / (1.f - BETA_);
        o = (o - ALPHA_ * g_st11[b * C_ + tid]) / (1.f - ALPHA_);
        out[b * C_ + tid] = o;
    }
}

// ---------------------------------------------------------------------------
extern "C" void kernel_launch(void* const* d_in, const int* in_sizes, int n_in,
                              void* d_out, int out_size) {
    const float* x    = (const float*)d_in[0];
    const float* W_ih = (const float*)d_in[1];
    const float* W_hh = (const float*)d_in[2];
    const float* b_ih = (const float*)d_in[3];
    const float* b_hh = (const float*)d_in[4];
    const float* W_fc = (const float*)d_in[5];
    const float* b_fc = (const float*)d_in[6];
    float* out = (float*)d_out;

    ema_kernel<<<B_ * (T_ / CH_), 64>>>(x);
    xp_gemm_kernel<<<(B_ * T_) / 64, 384>>>(W_ih, b_ih);
    gru_kernel<<<B_, 256>>>(W_hh, b_hh, W_fc, b_fc, out);
}